// round 10
// baseline (speedup 1.0000x reference)
#include <cuda_runtime.h>
#include <cuda_fp8.h>
#include <cuda_fp16.h>
#include <cstdint>

#define VOCAB 100000
#define BATCH 65536
#define NEG 5
#define WPB 8
#define THREADS 256
#define GRID 1184                 // 148 SMs * 8 blocks
#define TW (GRID * WPB)           // 9472 warps

#define VSCALE 64.0f
#define INV_VSCALE 0.015625f

// fp8(e4m3) copy of v_table, scaled by 64. 100000*32 u32 = 12.8 MB.
__device__ uint32_t g_v8[VOCAB * 32];
__device__ float g_partials[GRID];
__device__ unsigned int g_done_count = 0;

// ---------------- conversion kernel: v_table f32 -> fp8*64 ----------------
__global__ __launch_bounds__(256) void convert_v(const float4* __restrict__ v4)
{
    int t = blockIdx.x * 256 + threadIdx.x;
    if (t >= VOCAB * 32) return;
    float4 f = v4[t];
    float2 a = make_float2(f.x * VSCALE, f.y * VSCALE);
    float2 b = make_float2(f.z * VSCALE, f.w * VSCALE);
    uint32_t lo = __nv_cvt_float2_to_fp8x2(a, __NV_SATFINITE, __NV_E4M3);
    uint32_t hi = __nv_cvt_float2_to_fp8x2(b, __NV_SATFINITE, __NV_E4M3);
    g_v8[t] = lo | (hi << 16);
}

// -------------------------------- main ------------------------------------
__device__ __forceinline__ __half2 raw2h2(__half2_raw r)
{
    __half2 h;
    *reinterpret_cast<__half2_raw*>(&h) = r;
    return h;
}

// dot of one fp8x4 v-chunk with w (as 2 half2), accumulated exactly in f32
__device__ __forceinline__ float dot_row(uint32_t v, __half2 w01, __half2 w23)
{
    __half2 v01 = raw2h2(__nv_cvt_fp8x2_to_halfraw2((__nv_fp8x2_storage_t)(v & 0xFFFFu), __NV_E4M3));
    __half2 v23 = raw2h2(__nv_cvt_fp8x2_to_halfraw2((__nv_fp8x2_storage_t)(v >> 16), __NV_E4M3));
    __half2 m = __hmul2(v01, w01);
    m = __hfma2(v23, w23, m);
    float2 f = __half22float2(m);
    return f.x + f.y;
}

__global__ __launch_bounds__(THREADS, 8) void sgneg_fused(
    const int* __restrict__ pos_w,
    const int* __restrict__ pos_v,
    const int* __restrict__ neg_v,
    const float4* __restrict__ w_table,
    float* __restrict__ out)
{
    const int lane = threadIdx.x & 31;
    const int wib  = threadIdx.x >> 5;
    const int gw   = blockIdx.x * WPB + wib;
    const unsigned FULL = 0xFFFFFFFFu;
    const uint32_t* __restrict__ v8 = g_v8;

    float acc = 0.0f;

    for (int b = gw; b < BATCH; b += TW) {
        // Indices (warp-uniform broadcast loads), 32-bit row offsets
        const int wi  = pos_w[b] << 5;
        const int pvi = pos_v[b] << 5;
        const int ni0 = neg_v[b * NEG + 0] << 5;
        const int ni1 = neg_v[b * NEG + 1] << 5;
        const int ni2 = neg_v[b * NEG + 2] << 5;
        const int ni3 = neg_v[b * NEG + 3] << 5;
        const int ni4 = neg_v[b * NEG + 4] << 5;

        // w: 512B gather (f32); v rows: 128B gathers (fp8, 1 line each)
        const float4   w  = w_table[wi + lane];
        const uint32_t p  = v8[pvi + lane];
        const uint32_t n0 = v8[ni0 + lane];
        const uint32_t n1 = v8[ni1 + lane];
        const uint32_t n2 = v8[ni2 + lane];
        const uint32_t n3 = v8[ni3 + lane];
        const uint32_t n4 = v8[ni4 + lane];

        const __half2 w01 = __floats2half2_rn(w.x, w.y);
        const __half2 w23 = __floats2half2_rn(w.z, w.w);

        float d0 = dot_row(p,  w01, w23);
        float d1 = dot_row(n0, w01, w23);
        float d2 = dot_row(n1, w01, w23);
        float d3 = dot_row(n2, w01, w23);
        float d4 = dot_row(n3, w01, w23);
        float d5 = dot_row(n4, w01, w23);

        // Packed 6-value warp reduction: 13 shuffles.
        float t, u;
        t = __shfl_xor_sync(FULL, d0, 16);
        u = __shfl_xor_sync(FULL, d1, 16);
        float e0 = (lane & 16) ? d1 + u : d0 + t;
        t = __shfl_xor_sync(FULL, d2, 16);
        u = __shfl_xor_sync(FULL, d3, 16);
        float e1 = (lane & 16) ? d3 + u : d2 + t;
        t = __shfl_xor_sync(FULL, d4, 16);
        u = __shfl_xor_sync(FULL, d5, 16);
        float e2 = (lane & 16) ? d5 + u : d4 + t;
        t = __shfl_xor_sync(FULL, e0, 8);
        u = __shfl_xor_sync(FULL, e1, 8);
        float f0 = (lane & 8) ? e1 + u : e0 + t;
        e2 += __shfl_xor_sync(FULL, e2, 8);
        t = __shfl_xor_sync(FULL, f0, 4);
        u = __shfl_xor_sync(FULL, e2, 4);
        float g = (lane & 4) ? e2 + u : f0 + t;
        g += __shfl_xor_sync(FULL, g, 2);
        g += __shfl_xor_sync(FULL, g, 1);

        // Undo the fp8 pre-scale, then clip + logsigmoid
        g *= INV_VSCALE;

        // Owner lanes: 0->pos, 16,8,24,4,20 -> negatives
        const bool active = ((lane & 3) == 0) && !((lane & 4) && (lane & 8));
        float x = fminf(fmaxf(g, -10.0f), 10.0f);
        if (lane != 0) x = -x;
        float term = -__logf(1.0f + __expf(-x));   // log_sigmoid, x in [-10,10]
        acc += active ? term : 0.0f;
    }

    // End-of-kernel warp reduction
#pragma unroll
    for (int off = 16; off > 0; off >>= 1)
        acc += __shfl_xor_sync(FULL, acc, off);

    __shared__ float sh[WPB];
    if (lane == 0) sh[wib] = acc;
    __syncthreads();

    __shared__ bool is_last;
    if (threadIdx.x == 0) {
        float s = 0.0f;
#pragma unroll
        for (int i = 0; i < WPB; i++) s += sh[i];
        g_partials[blockIdx.x] = s;
        __threadfence();
        unsigned int old = atomicAdd(&g_done_count, 1u);
        is_last = (old == (unsigned int)(GRID - 1));
    }
    __syncthreads();

    if (is_last) {
        __shared__ double shd[THREADS];
        double s = 0.0;
        for (int i = threadIdx.x; i < GRID; i += THREADS)
            s += (double)g_partials[i];
        shd[threadIdx.x] = s;
        __syncthreads();
#pragma unroll
        for (int st = THREADS / 2; st > 0; st >>= 1) {
            if (threadIdx.x < st) shd[threadIdx.x] += shd[threadIdx.x + st];
            __syncthreads();
        }
        if (threadIdx.x == 0) {
            out[0] = (float)(-shd[0]);
            g_done_count = 0;   // reset for next graph replay
        }
    }
}

extern "C" void kernel_launch(void* const* d_in, const int* in_sizes, int n_in,
                              void* d_out, int out_size)
{
    const int*    pos_w   = (const int*)d_in[0];
    const int*    pos_v   = (const int*)d_in[1];
    const int*    neg_v   = (const int*)d_in[2];
    const float4* w_table = (const float4*)d_in[3];
    const float4* v_table = (const float4*)d_in[4];
    float*        out     = (float*)d_out;

    const int n4 = VOCAB * 32;                       // 3.2M u32 outputs
    convert_v<<<(n4 + 255) / 256, 256>>>(v_table);
    sgneg_fused<<<GRID, THREADS>>>(pos_w, pos_v, neg_v, w_table, out);
}

// round 11
// speedup vs baseline: 1.2971x; 1.2971x over previous
#include <cuda_runtime.h>
#include <cuda_fp8.h>
#include <cuda_fp16.h>
#include <cstdint>

#define VOCAB 100000
#define BATCH 65536
#define PAIRS (BATCH / 2)
#define NEG 5
#define WPB 8
#define THREADS 256
#define GRID 740                  // 148 SMs * 5 blocks -> one wave at <=51 regs
#define TW (GRID * WPB)           // 5920 warps

#define VSCALE 64.0f
#define INV_VSCALE 0.015625f

// fp8(e4m3) copy of v_table, scaled by 64. Stored as u64 (8 fp8 per word).
__device__ uint64_t g_v8[VOCAB * 16];
__device__ float g_partials[GRID];
__device__ unsigned int g_done_count = 0;

// -------------- conversion kernel: v_table f32 -> fp8*64 (u64 out) ---------
__global__ __launch_bounds__(256) void convert_v(const float4* __restrict__ v4)
{
    int t = blockIdx.x * 256 + threadIdx.x;
    if (t >= VOCAB * 16) return;
    float4 f0 = __ldcs(&v4[2 * t]);          // streaming: don't pollute L2
    float4 f1 = __ldcs(&v4[2 * t + 1]);
    uint32_t a = __nv_cvt_float2_to_fp8x2(make_float2(f0.x * VSCALE, f0.y * VSCALE), __NV_SATFINITE, __NV_E4M3);
    uint32_t b = __nv_cvt_float2_to_fp8x2(make_float2(f0.z * VSCALE, f0.w * VSCALE), __NV_SATFINITE, __NV_E4M3);
    uint32_t c = __nv_cvt_float2_to_fp8x2(make_float2(f1.x * VSCALE, f1.y * VSCALE), __NV_SATFINITE, __NV_E4M3);
    uint32_t d = __nv_cvt_float2_to_fp8x2(make_float2(f1.z * VSCALE, f1.w * VSCALE), __NV_SATFINITE, __NV_E4M3);
    uint64_t lo = (uint64_t)(a | (b << 16));
    uint64_t hi = (uint64_t)(c | (d << 16));
    g_v8[t] = lo | (hi << 32);
}

// -------------------------------- main ------------------------------------
__device__ __forceinline__ __half2 raw2h2(__half2_raw r)
{
    __half2 h;
    *reinterpret_cast<__half2_raw*>(&h) = r;
    return h;
}

// dot of 8 fp8 (u64) with 8 w-halfs (4 half2), f32 result
__device__ __forceinline__ float dot8(uint64_t v, __half2 w0, __half2 w1,
                                      __half2 w2, __half2 w3)
{
    uint32_t lo = (uint32_t)v, hi = (uint32_t)(v >> 32);
    __half2 a = raw2h2(__nv_cvt_fp8x2_to_halfraw2((__nv_fp8x2_storage_t)(lo & 0xFFFFu), __NV_E4M3));
    __half2 b = raw2h2(__nv_cvt_fp8x2_to_halfraw2((__nv_fp8x2_storage_t)(lo >> 16),    __NV_E4M3));
    __half2 c = raw2h2(__nv_cvt_fp8x2_to_halfraw2((__nv_fp8x2_storage_t)(hi & 0xFFFFu), __NV_E4M3));
    __half2 d = raw2h2(__nv_cvt_fp8x2_to_halfraw2((__nv_fp8x2_storage_t)(hi >> 16),    __NV_E4M3));
    __half2 m = __hmul2(a, w0);
    m = __hfma2(b, w1, m);
    m = __hfma2(c, w2, m);
    m = __hfma2(d, w3, m);
    float2 f = __half22float2(m);
    return f.x + f.y;
}

__global__ __launch_bounds__(THREADS, 5) void sgneg_fused(
    const int* __restrict__ pos_w,
    const int* __restrict__ pos_v,
    const int* __restrict__ neg_v,
    const float4* __restrict__ w_table,
    float* __restrict__ out)
{
    const int lane = threadIdx.x & 31;
    const int wib  = threadIdx.x >> 5;
    const int gw   = blockIdx.x * WPB + wib;
    const int half = lane >> 4;         // which element of the pair
    const int hl   = lane & 15;         // lane within half-warp
    const unsigned FULL = 0xFFFFFFFFu;
    const uint64_t* __restrict__ v8 = g_v8;

    float acc = 0.0f;

    for (int pr = gw; pr < PAIRS; pr += TW) {
        const int e = 2 * pr + half;    // this half-warp's element

        // Indices (uniform per half-warp), row offsets:
        //   w_table in float4 units (<<5), v8 in u64 units (<<4)
        const int wi  = pos_w[e] << 5;
        const int pvi = pos_v[e] << 4;
        const int ni0 = neg_v[e * NEG + 0] << 4;
        const int ni1 = neg_v[e * NEG + 1] << 4;
        const int ni2 = neg_v[e * NEG + 2] << 4;
        const int ni3 = neg_v[e * NEG + 3] << 4;
        const int ni4 = neg_v[e * NEG + 4] << 4;

        // w: 8 floats/lane (2 float4); v rows: 8 fp8/lane (1 u64, 128B/half)
        const float4   wa = w_table[wi + 2 * hl];
        const float4   wb = w_table[wi + 2 * hl + 1];
        const uint64_t p  = v8[pvi + hl];
        const uint64_t n0 = v8[ni0 + hl];
        const uint64_t n1 = v8[ni1 + hl];
        const uint64_t n2 = v8[ni2 + hl];
        const uint64_t n3 = v8[ni3 + hl];
        const uint64_t n4 = v8[ni4 + hl];

        const __half2 w0 = __floats2half2_rn(wa.x, wa.y);
        const __half2 w1 = __floats2half2_rn(wa.z, wa.w);
        const __half2 w2 = __floats2half2_rn(wb.x, wb.y);
        const __half2 w3 = __floats2half2_rn(wb.z, wb.w);

        float d0 = dot8(p,  w0, w1, w2, w3);
        float d1 = dot8(n0, w0, w1, w2, w3);
        float d2 = dot8(n1, w0, w1, w2, w3);
        float d3 = dot8(n2, w0, w1, w2, w3);
        float d4 = dot8(n3, w0, w1, w2, w3);
        float d5 = dot8(n4, w0, w1, w2, w3);

        // Packed 6-value reduction within each 16-lane half: 12 shuffles
        // (offsets 8,4,2,1 never cross the half boundary).
        float t, u;
        t = __shfl_xor_sync(FULL, d0, 8);
        u = __shfl_xor_sync(FULL, d1, 8);
        float e0 = (hl & 8) ? d1 + u : d0 + t;
        t = __shfl_xor_sync(FULL, d2, 8);
        u = __shfl_xor_sync(FULL, d3, 8);
        float e1 = (hl & 8) ? d3 + u : d2 + t;
        t = __shfl_xor_sync(FULL, d4, 8);
        u = __shfl_xor_sync(FULL, d5, 8);
        float e2 = (hl & 8) ? d5 + u : d4 + t;
        t = __shfl_xor_sync(FULL, e0, 4);
        u = __shfl_xor_sync(FULL, e1, 4);
        float f0 = (hl & 4) ? e1 + u : e0 + t;
        e2 += __shfl_xor_sync(FULL, e2, 4);
        t = __shfl_xor_sync(FULL, f0, 2);
        u = __shfl_xor_sync(FULL, e2, 2);
        float g = (hl & 2) ? e2 + u : f0 + t;
        g += __shfl_xor_sync(FULL, g, 1);

        // Owner lanes per half: hl in {0,8,4,12,2,10}; hl==0 is the positive
        const bool active = ((hl & 1) == 0) && !((hl & 2) && (hl & 4));
        g *= INV_VSCALE;                      // undo fp8 pre-scale
        float x = fminf(fmaxf(g, -10.0f), 10.0f);
        if (hl != 0) x = -x;
        float term = -__logf(1.0f + __expf(-x));   // log_sigmoid, x in [-10,10]
        acc += active ? term : 0.0f;
    }

    // End-of-kernel full-warp reduction of acc
#pragma unroll
    for (int off = 16; off > 0; off >>= 1)
        acc += __shfl_xor_sync(FULL, acc, off);

    __shared__ float sh[WPB];
    if (lane == 0) sh[wib] = acc;
    __syncthreads();

    __shared__ bool is_last;
    if (threadIdx.x == 0) {
        float s = 0.0f;
#pragma unroll
        for (int i = 0; i < WPB; i++) s += sh[i];
        g_partials[blockIdx.x] = s;
        __threadfence();
        unsigned int old = atomicAdd(&g_done_count, 1u);
        is_last = (old == (unsigned int)(GRID - 1));
    }
    __syncthreads();

    if (is_last) {
        __shared__ double shd[THREADS];
        double s = 0.0;
        for (int i = threadIdx.x; i < GRID; i += THREADS)
            s += (double)g_partials[i];
        shd[threadIdx.x] = s;
        __syncthreads();
#pragma unroll
        for (int st = THREADS / 2; st > 0; st >>= 1) {
            if (threadIdx.x < st) shd[threadIdx.x] += shd[threadIdx.x + st];
            __syncthreads();
        }
        if (threadIdx.x == 0) {
            out[0] = (float)(-shd[0]);
            g_done_count = 0;   // reset for next graph replay
        }
    }
}

extern "C" void kernel_launch(void* const* d_in, const int* in_sizes, int n_in,
                              void* d_out, int out_size)
{
    const int*    pos_w   = (const int*)d_in[0];
    const int*    pos_v   = (const int*)d_in[1];
    const int*    neg_v   = (const int*)d_in[2];
    const float4* w_table = (const float4*)d_in[3];
    const float4* v_table = (const float4*)d_in[4];
    float*        out     = (float*)d_out;

    const int n64 = VOCAB * 16;                      // 1.6M u64 outputs
    convert_v<<<(n64 + 255) / 256, 256>>>(v_table);
    sgneg_fused<<<GRID, THREADS>>>(pos_w, pos_v, neg_v, w_table, out);
}